// round 9
// baseline (speedup 1.0000x reference)
#include <cuda_runtime.h>
#include <cuda_bf16.h>
#include <cuda_fp16.h>
#include <cuda_fp8.h>
#include <math.h>
#include <stdint.h>

#define TWO_B 128
#define KCH   256
#define MSZ   512
#define DIM   256
#define NROWS (TWO_B * KCH)   // 32768
#define EPSN  1e-8f
#define SELF_E2 7.38905609893065f   // exp(2) = diagonal term to subtract

// fp8 normalized rows, batch-major [b][i][d], scaled by 16/sqrt(2): 16 MB
__device__ uint8_t g_z8[(size_t)TWO_B * MSZ * DIM];
// per-row exp-sum partials: [b][row_tile][slot][row_in_tile], each written once
__device__ float g_rowpart[TWO_B][4][4][128];
__device__ float g_pos_part[NROWS / 8];
__device__ float g_neg_part[TWO_B];
__device__ unsigned g_ctr;
__device__ unsigned g_bctr[TWO_B];

__constant__ int TI_LUT[10] = {0,0,0,0,1,1,1,2,2,3};
__constant__ int TJ_LUT[10] = {0,1,2,3,1,2,3,2,3,3};

// ---------------- helpers ----------------
__device__ __forceinline__ uint32_t smem_u32(const void* p) {
    uint32_t a;
    asm("{ .reg .u64 t; cvta.to.shared.u64 t, %1; cvt.u32.u64 %0, t; }"
        : "=r"(a) : "l"(p));
    return a;
}

#define CP_ASYNC16(sdst, gsrc) \
    asm volatile("cp.async.cg.shared.global [%0], [%1], 16;" \
                 :: "r"(sdst), "l"(gsrc) : "memory")
#define CP_COMMIT() asm volatile("cp.async.commit_group;" ::: "memory")
#define CP_WAIT0()  asm volatile("cp.async.wait_group 0;" ::: "memory")

#define LDMATRIX_X4(r, addr) \
    asm volatile("ldmatrix.sync.aligned.m8n8.x4.shared.b16 {%0,%1,%2,%3}, [%4];" \
                 : "=r"((r)[0]), "=r"((r)[1]), "=r"((r)[2]), "=r"((r)[3]) \
                 : "r"(addr))

#define MMA_FP8(c, a, b0, b1) \
    asm volatile("mma.sync.aligned.m16n8k32.row.col.f32.e4m3.e4m3.f32 " \
                 "{%0,%1,%2,%3},{%4,%5,%6,%7},{%8,%9},{%0,%1,%2,%3};" \
                 : "+f"((c)[0]), "+f"((c)[1]), "+f"((c)[2]), "+f"((c)[3]) \
                 : "r"((a)[0]), "r"((a)[1]), "r"((a)[2]), "r"((a)[3]), \
                   "r"(b0), "r"(b1))

// Tile: 128 rows x 256 fp8 (256B/row); cb = 16B column 0..15, XOR-swizzled
__device__ __forceinline__ uint32_t swz8(uint32_t r, uint32_t cb) {
    return r * 256u + ((cb ^ (r & 7u)) << 4);
}

__device__ __forceinline__ uint32_t pack_fp8x4(float a, float b, float c, float d) {
    __nv_fp8x2_storage_t lo = __nv_cvt_float2_to_fp8x2(make_float2(a, b),
                                                       __NV_SATFINITE, __NV_E4M3);
    __nv_fp8x2_storage_t hi = __nv_cvt_float2_to_fp8x2(make_float2(c, d),
                                                       __NV_SATFINITE, __NV_E4M3);
    return (uint32_t)lo | ((uint32_t)hi << 16);
}

// half2 2^x via MUFU (both lanes in one op)
__device__ __forceinline__ __half2 ex2_h2(__half2 v) {
    uint32_t r, a = *(uint32_t*)&v;
    asm("ex2.approx.f16x2 %0, %1;" : "=r"(r) : "r"(a));
    return *(__half2*)&r;
}

// ---------------- kernels ----------------
// One warp per row: norms + cosine; write scaled normalized fp8 rows batch-major.
__global__ void normalize_kernel(const float* __restrict__ x,
                                 const float* __restrict__ xp) {
    if (threadIdx.x == 0) {
        if (blockIdx.x == 0) g_ctr = 0;
        if (blockIdx.x < TWO_B) g_bctr[blockIdx.x] = 0;
    }

    int wib  = threadIdx.x >> 5;
    int lane = threadIdx.x & 31;
    int row  = blockIdx.x * 8 + wib;

    const float4* xr = (const float4*)(x  + (size_t)row * DIM);
    const float4* pr = (const float4*)(xp + (size_t)row * DIM);
    float4 xa = xr[lane], xb = xr[lane + 32];
    float4 pa = pr[lane], pb = pr[lane + 32];

    float ssx = xa.x*xa.x + xa.y*xa.y + xa.z*xa.z + xa.w*xa.w
              + xb.x*xb.x + xb.y*xb.y + xb.z*xb.z + xb.w*xb.w;
    float ssp = pa.x*pa.x + pa.y*pa.y + pa.z*pa.z + pa.w*pa.w
              + pb.x*pb.x + pb.y*pb.y + pb.z*pb.z + pb.w*pb.w;
    float dt  = xa.x*pa.x + xa.y*pa.y + xa.z*pa.z + xa.w*pa.w
              + xb.x*pb.x + xb.y*pb.y + xb.z*pb.z + xb.w*pb.w;

    #pragma unroll
    for (int o = 16; o > 0; o >>= 1) {
        ssx += __shfl_down_sync(0xffffffffu, ssx, o);
        ssp += __shfl_down_sync(0xffffffffu, ssp, o);
        dt  += __shfl_down_sync(0xffffffffu, dt,  o);
    }
    ssx = __shfl_sync(0xffffffffu, ssx, 0);
    ssp = __shfl_sync(0xffffffffu, ssp, 0);
    dt  = __shfl_sync(0xffffffffu, dt,  0);

    float nx = fmaxf(sqrtf(ssx), EPSN);
    float np = fmaxf(sqrtf(ssp), EPSN);
    float cosv = dt / (nx * np);

    // scale = 16/sqrt(2): stored dot = 128*cos = c, sim/TEMP = c/64
    const float SCL = 11.313708498984761f;
    float sx = SCL / nx;
    float sp = SCL / np;
    int b = row & (TWO_B - 1);
    int i = row >> 7;

    uint8_t* zx = g_z8 + ((size_t)b * MSZ + i)       * DIM;
    uint8_t* zp = g_z8 + ((size_t)b * MSZ + i + KCH) * DIM;
    *(uint32_t*)(zx + 4 * lane)       = pack_fp8x4(xa.x*sx, xa.y*sx, xa.z*sx, xa.w*sx);
    *(uint32_t*)(zx + 128 + 4 * lane) = pack_fp8x4(xb.x*sx, xb.y*sx, xb.z*sx, xb.w*sx);
    *(uint32_t*)(zp + 4 * lane)       = pack_fp8x4(pa.x*sp, pa.y*sp, pa.z*sp, pa.w*sp);
    *(uint32_t*)(zp + 128 + 4 * lane) = pack_fp8x4(pb.x*sp, pb.y*sp, pb.z*sp, pb.w*sp);

    __shared__ float psum[8];
    if (lane == 0) psum[wib] = cosv;
    __syncthreads();
    if (threadIdx.x == 0) {
        float s = 0.f;
        #pragma unroll
        for (int q = 0; q < 8; q++) s += psum[q];
        g_pos_part[blockIdx.x] = s;
    }
}

// One CTA = one (b, ti<=tj) tile pair; the CTA that completes a batch also
// does that batch's lse; the CTA that completes the last batch writes out.
__global__ __launch_bounds__(256, 2) void gram_kernel(float* __restrict__ out) {
    __shared__ float red[128][4];
    __shared__ float colred[128][2];
    extern __shared__ char dyn[];

    int t    = threadIdx.x;
    int wid  = t >> 5;
    int lane = t & 31;
    int b    = blockIdx.y;
    int p    = blockIdx.x;
    int ti   = TI_LUT[p];
    int tj   = TJ_LUT[p];
    bool diag = (ti == tj);

    int wm = wid >> 2;          // 0..1 : warp m-offset = wm*64
    int wn = wid & 3;           // 0..3 : warp n-offset = wn*32

    uint32_t sA = smem_u32(dyn);
    uint32_t sBj = diag ? sA : (sA + 32768);

    const uint8_t* Z = g_z8 + (size_t)b * MSZ * DIM;
    {   // load tiles: 2048 16B chunks each (32KB)
        const char* gA = (const char*)(Z + (size_t)ti * 128 * DIM);
        const char* gB = (const char*)(Z + (size_t)tj * 128 * DIM);
        #pragma unroll
        for (int q = 0; q < 8; q++) {
            int f = t + q * 256;
            uint32_t off = swz8(f >> 4, f & 15);
            CP_ASYNC16(sA + off, gA + (size_t)f * 16);
            if (!diag) CP_ASYNC16(sBj + off, gB + (size_t)f * 16);
        }
        CP_COMMIT();
        CP_WAIT0();
        __syncthreads();
    }

    float C[4][4][4];
    #pragma unroll
    for (int mt = 0; mt < 4; mt++)
        #pragma unroll
        for (int nt = 0; nt < 4; nt++)
            #pragma unroll
            for (int e = 0; e < 4; e++) C[mt][nt][e] = 0.f;

    #pragma unroll
    for (int k = 0; k < 8; k++) {           // 8 steps of k=32 fp8
        uint32_t cb = 2u * k + (lane >> 4);
        uint32_t afr[4][4], bfr[2][4];
        #pragma unroll
        for (int mt = 0; mt < 4; mt++) {
            uint32_t r = wm * 64 + mt * 16 + (lane & 15);
            LDMATRIX_X4(afr[mt], sA + swz8(r, cb));
        }
        #pragma unroll
        for (int h = 0; h < 2; h++) {
            uint32_t r = wn * 32 + h * 16 + (lane & 15);
            LDMATRIX_X4(bfr[h], sBj + swz8(r, cb));
        }
        #pragma unroll
        for (int mt = 0; mt < 4; mt++)
            #pragma unroll
            for (int nt = 0; nt < 4; nt++) {
                uint32_t b0 = bfr[nt >> 1][(nt & 1) ? 1 : 0];
                uint32_t b1 = bfr[nt >> 1][(nt & 1) ? 3 : 2];
                MMA_FP8(C[mt][nt], afr[mt], b0, b1);
            }
    }

    // epilogue: branch-free; exp via one MUFU f16x2 per element-pair
    const __half2 K2H = __floats2half2_rn(0.022556390446879415f,
                                          0.022556390446879415f);
    __half2 rowh[8], colh[4];
    #pragma unroll
    for (int q = 0; q < 8; q++) rowh[q] = __floats2half2_rn(0.f, 0.f);
    #pragma unroll
    for (int q = 0; q < 4; q++) colh[q] = __floats2half2_rn(0.f, 0.f);

    #pragma unroll
    for (int mt = 0; mt < 4; mt++) {
        #pragma unroll
        for (int nt = 0; nt < 4; nt++) {
            #pragma unroll
            for (int h = 0; h < 2; h++) {
                __half2 hv = __floats2half2_rn(C[mt][nt][h * 2 + 0],
                                               C[mt][nt][h * 2 + 1]);
                __half2 ev = ex2_h2(__hmul2(hv, K2H));
                rowh[mt * 2 + h] = __hadd2(rowh[mt * 2 + h], ev);
                colh[nt] = __hadd2(colh[nt], ev);
            }
        }
    }

    float rowacc[8], colacc[8];
    #pragma unroll
    for (int q = 0; q < 8; q++) {
        float2 f = __half22float2(rowh[q]);
        rowacc[q] = f.x + f.y;
    }
    #pragma unroll
    for (int nt = 0; nt < 4; nt++) {
        float2 f = __half22float2(colh[nt]);
        colacc[nt * 2 + 0] = f.x;
        colacc[nt * 2 + 1] = f.y;
    }

    // row reduction: over lane&3, then over wn via smem
    #pragma unroll
    for (int q = 0; q < 8; q++) {
        rowacc[q] += __shfl_xor_sync(0xffffffffu, rowacc[q], 1);
        rowacc[q] += __shfl_xor_sync(0xffffffffu, rowacc[q], 2);
    }
    if ((lane & 3) == 0) {
        #pragma unroll
        for (int mt = 0; mt < 4; mt++)
            #pragma unroll
            for (int h = 0; h < 2; h++)
                red[wm * 64 + mt * 16 + (lane >> 2) + 8 * h][wn] =
                    rowacc[mt * 2 + h];
    }

    // col reduction (off-diag only): over lane>>2, then over wm
    if (!diag) {
        #pragma unroll
        for (int q = 0; q < 8; q++) {
            colacc[q] += __shfl_xor_sync(0xffffffffu, colacc[q], 4);
            colacc[q] += __shfl_xor_sync(0xffffffffu, colacc[q], 8);
            colacc[q] += __shfl_xor_sync(0xffffffffu, colacc[q], 16);
        }
        if (lane < 4) {
            #pragma unroll
            for (int nt = 0; nt < 4; nt++)
                #pragma unroll
                for (int e = 0; e < 2; e++)
                    colred[wn * 32 + nt * 8 + lane * 2 + e][wm] =
                        colacc[nt * 2 + e];
        }
    }
    __syncthreads();

    if (t < 128) {
        g_rowpart[b][ti][tj][t] = red[t][0] + red[t][1]
                                + red[t][2] + red[t][3];
        if (!diag)
            g_rowpart[b][tj][ti][t] = colred[t][0] + colred[t][1];
    }

    // ---- fused batch lse + final reduction ----
    __threadfence();
    __syncthreads();
    __shared__ unsigned oldc;
    if (t == 0) oldc = atomicAdd(&g_bctr[b], 1u);
    __syncthreads();
    if (oldc != 9) return;   // not the batch finisher

    // this CTA completes batch b: lse over its 512 rows
    float lsum = 0.f;
    #pragma unroll
    for (int h = 0; h < 2; h++) {
        int rr = t + h * 256;
        int tr = rr >> 7, r = rr & 127;
        const float* rp = &g_rowpart[b][tr][0][0];
        float s = __ldcg(rp + r) + __ldcg(rp + 128 + r)
                + __ldcg(rp + 256 + r) + __ldcg(rp + 384 + r)
                - SELF_E2;
        lsum += logf(s);
    }
    __shared__ float wsum[8];
    #pragma unroll
    for (int o = 16; o > 0; o >>= 1)
        lsum += __shfl_down_sync(0xffffffffu, lsum, o);
    if (lane == 0) wsum[wid] = lsum;
    __syncthreads();
    __shared__ unsigned oldb;
    if (t == 0) {
        float acc = 0.f;
        #pragma unroll
        for (int q = 0; q < 8; q++) acc += wsum[q];
        g_neg_part[b] = acc;
        __threadfence();
        oldb = atomicAdd(&g_ctr, 1u);
    }
    __syncthreads();
    if (oldb != TWO_B - 1) return;   // not the global finisher

    // final combine
    double dp = 0.0, dn = 0.0;
    #pragma unroll
    for (int q = 0; q < 16; q++) dp += (double)__ldcg(&g_pos_part[t + q * 256]);
    if (t < TWO_B) dn = (double)__ldcg(&g_neg_part[t]);

    __shared__ double wp[8], wng[8];
    #pragma unroll
    for (int o = 16; o > 0; o >>= 1) {
        dp += __shfl_down_sync(0xffffffffu, dp, o);
        dn += __shfl_down_sync(0xffffffffu, dn, o);
    }
    if (lane == 0) { wp[wid] = dp; wng[wid] = dn; }
    __syncthreads();
    if (t == 0) {
        double sp = 0.0, sn = 0.0;
        #pragma unroll
        for (int q = 0; q < 8; q++) { sp += wp[q]; sn += wng[q]; }
        double loss_neg = sn / (double)(TWO_B * MSZ);
        double loss_pos = (sp / (double)NROWS) * 2.0;
        out[0] = (float)(loss_neg - loss_pos);
    }
}

extern "C" void kernel_launch(void* const* d_in, const int* in_sizes, int n_in,
                              void* d_out, int out_size) {
    const float* x  = (const float*)d_in[0];
    const float* xp = (const float*)d_in[1];
    float* out = (float*)d_out;

    cudaFuncSetAttribute(gram_kernel,
                         cudaFuncAttributeMaxDynamicSharedMemorySize, 65536);

    normalize_kernel<<<NROWS / 8, 256>>>(x, xp);
    dim3 grid(10, TWO_B);   // 10 tile pairs x 128 batches
    gram_kernel<<<grid, 256, 65536>>>(out);
}

// round 10
// speedup vs baseline: 1.1176x; 1.1176x over previous
#include <cuda_runtime.h>
#include <cuda_bf16.h>
#include <cuda_fp16.h>
#include <cuda_fp8.h>
#include <math.h>
#include <stdint.h>

#define TWO_B 128
#define KCH   256
#define MSZ   512
#define DIM   256
#define NROWS (TWO_B * KCH)   // 32768
#define EPSN  1e-8f
#define SELF_E2 7.38905609893065f   // exp(2) diagonal term subtracted in lse
#define NP 36                       // 8*9/2 tile pairs (64-row tiles)

// fp8 normalized rows, batch-major [b][i][d], scaled by 16/sqrt(2): 16 MB
__device__ uint8_t g_z8[(size_t)TWO_B * MSZ * DIM];
// per-row exp-sum partials: [b][row_tile(8)][slot(8)][row(64)], each written once
__device__ float g_rowpart[TWO_B][8][8][64];   // 1 MB
__device__ float g_pos_part[NROWS / 8];
__device__ float g_neg_part[TWO_B];
__device__ unsigned g_ctr;

__constant__ unsigned char TI_LUT[NP] = {
    0,0,0,0,0,0,0,0, 1,1,1,1,1,1,1, 2,2,2,2,2,2, 3,3,3,3,3,
    4,4,4,4, 5,5,5, 6,6, 7};
__constant__ unsigned char TJ_LUT[NP] = {
    0,1,2,3,4,5,6,7, 1,2,3,4,5,6,7, 2,3,4,5,6,7, 3,4,5,6,7,
    4,5,6,7, 5,6,7, 6,7, 7};

// ---------------- helpers ----------------
__device__ __forceinline__ uint32_t smem_u32(const void* p) {
    uint32_t a;
    asm("{ .reg .u64 t; cvta.to.shared.u64 t, %1; cvt.u32.u64 %0, t; }"
        : "=r"(a) : "l"(p));
    return a;
}

#define CP_ASYNC16(sdst, gsrc) \
    asm volatile("cp.async.cg.shared.global [%0], [%1], 16;" \
                 :: "r"(sdst), "l"(gsrc) : "memory")
#define CP_COMMIT() asm volatile("cp.async.commit_group;" ::: "memory")
#define CP_WAIT0()  asm volatile("cp.async.wait_group 0;" ::: "memory")

#define LDMATRIX_X4(r, addr) \
    asm volatile("ldmatrix.sync.aligned.m8n8.x4.shared.b16 {%0,%1,%2,%3}, [%4];" \
                 : "=r"((r)[0]), "=r"((r)[1]), "=r"((r)[2]), "=r"((r)[3]) \
                 : "r"(addr))

#define MMA_FP8(c, a0, a1, b0, b1) \
    asm volatile("mma.sync.aligned.m16n8k32.row.col.f32.e4m3.e4m3.f32 " \
                 "{%0,%1,%2,%3},{%4,%5,%6,%7},{%8,%9},{%0,%1,%2,%3};" \
                 : "+f"((c)[0]), "+f"((c)[1]), "+f"((c)[2]), "+f"((c)[3]) \
                 : "r"(a0), "r"(a1), "r"((c)[0] == (c)[0] ? (a0) : (a0)), "r"(a1), \
                   "r"(b0), "r"(b1))

// (clean 4-reg A variant)
#define MMA_FP8A(c, a, b0, b1) \
    asm volatile("mma.sync.aligned.m16n8k32.row.col.f32.e4m3.e4m3.f32 " \
                 "{%0,%1,%2,%3},{%4,%5,%6,%7},{%8,%9},{%0,%1,%2,%3};" \
                 : "+f"((c)[0]), "+f"((c)[1]), "+f"((c)[2]), "+f"((c)[3]) \
                 : "r"((a)[0]), "r"((a)[1]), "r"((a)[2]), "r"((a)[3]), \
                   "r"(b0), "r"(b1))

// 64 rows x 256 fp8 tile (256B/row); cb = 16B column 0..15, XOR-swizzled
__device__ __forceinline__ uint32_t swz8(uint32_t r, uint32_t cb) {
    return r * 256u + ((cb ^ (r & 7u)) << 4);
}

__device__ __forceinline__ uint32_t pack_fp8x4(float a, float b, float c, float d) {
    __nv_fp8x2_storage_t lo = __nv_cvt_float2_to_fp8x2(make_float2(a, b),
                                                       __NV_SATFINITE, __NV_E4M3);
    __nv_fp8x2_storage_t hi = __nv_cvt_float2_to_fp8x2(make_float2(c, d),
                                                       __NV_SATFINITE, __NV_E4M3);
    return (uint32_t)lo | ((uint32_t)hi << 16);
}

// half2 2^x via MUFU (both lanes in one op)
__device__ __forceinline__ __half2 ex2_h2(__half2 v) {
    uint32_t r, a = *(uint32_t*)&v;
    asm("ex2.approx.f16x2 %0, %1;" : "=r"(r) : "r"(a));
    return *(__half2*)&r;
}

// ---------------- kernels ----------------
// One warp per row: norms + cosine; write scaled normalized fp8 rows batch-major.
__global__ void normalize_kernel(const float* __restrict__ x,
                                 const float* __restrict__ xp) {
    if (blockIdx.x == 0 && threadIdx.x == 0) g_ctr = 0;

    int wib  = threadIdx.x >> 5;
    int lane = threadIdx.x & 31;
    int row  = blockIdx.x * 8 + wib;

    const float4* xr = (const float4*)(x  + (size_t)row * DIM);
    const float4* pr = (const float4*)(xp + (size_t)row * DIM);
    float4 xa = xr[lane], xb = xr[lane + 32];
    float4 pa = pr[lane], pb = pr[lane + 32];

    float ssx = xa.x*xa.x + xa.y*xa.y + xa.z*xa.z + xa.w*xa.w
              + xb.x*xb.x + xb.y*xb.y + xb.z*xb.z + xb.w*xb.w;
    float ssp = pa.x*pa.x + pa.y*pa.y + pa.z*pa.z + pa.w*pa.w
              + pb.x*pb.x + pb.y*pb.y + pb.z*pb.z + pb.w*pb.w;
    float dt  = xa.x*pa.x + xa.y*pa.y + xa.z*pa.z + xa.w*pa.w
              + xb.x*pb.x + xb.y*pb.y + xb.z*pb.z + xb.w*pb.w;

    #pragma unroll
    for (int o = 16; o > 0; o >>= 1) {
        ssx += __shfl_down_sync(0xffffffffu, ssx, o);
        ssp += __shfl_down_sync(0xffffffffu, ssp, o);
        dt  += __shfl_down_sync(0xffffffffu, dt,  o);
    }
    ssx = __shfl_sync(0xffffffffu, ssx, 0);
    ssp = __shfl_sync(0xffffffffu, ssp, 0);
    dt  = __shfl_sync(0xffffffffu, dt,  0);

    float nx = fmaxf(sqrtf(ssx), EPSN);
    float np = fmaxf(sqrtf(ssp), EPSN);
    float cosv = dt / (nx * np);

    // scale = 16/sqrt(2): stored dot = 128*cos = c, sim/TEMP = c/64
    const float SCL = 11.313708498984761f;
    float sx = SCL / nx;
    float sp = SCL / np;
    int b = row & (TWO_B - 1);
    int i = row >> 7;

    uint8_t* zx = g_z8 + ((size_t)b * MSZ + i)       * DIM;
    uint8_t* zp = g_z8 + ((size_t)b * MSZ + i + KCH) * DIM;
    *(uint32_t*)(zx + 4 * lane)       = pack_fp8x4(xa.x*sx, xa.y*sx, xa.z*sx, xa.w*sx);
    *(uint32_t*)(zx + 128 + 4 * lane) = pack_fp8x4(xb.x*sx, xb.y*sx, xb.z*sx, xb.w*sx);
    *(uint32_t*)(zp + 4 * lane)       = pack_fp8x4(pa.x*sp, pa.y*sp, pa.z*sp, pa.w*sp);
    *(uint32_t*)(zp + 128 + 4 * lane) = pack_fp8x4(pb.x*sp, pb.y*sp, pb.z*sp, pb.w*sp);

    __shared__ float psum[8];
    if (lane == 0) psum[wib] = cosv;
    __syncthreads();
    if (threadIdx.x == 0) {
        float s = 0.f;
        #pragma unroll
        for (int q = 0; q < 8; q++) s += psum[q];
        g_pos_part[blockIdx.x] = s;
    }
}

// One CTA = one (b, ti<=tj) 64x64 tile pair. 4 warps, high occupancy.
__global__ __launch_bounds__(128, 6) void gram_kernel() {
    __shared__ float red[64][2];
    __shared__ float colred[64][2];
    extern __shared__ char dyn[];

    int t    = threadIdx.x;
    int wid  = t >> 5;
    int lane = t & 31;
    int b    = blockIdx.y;
    int p    = blockIdx.x;
    int ti   = TI_LUT[p];
    int tj   = TJ_LUT[p];
    bool diag = (ti == tj);

    int wm = wid >> 1;          // 0..1 : warp m-offset = wm*32
    int wn = wid & 1;           // 0..1 : warp n-offset = wn*32

    uint32_t sA = smem_u32(dyn);
    uint32_t sBj = diag ? sA : (sA + 16384);

    const uint8_t* Z = g_z8 + (size_t)b * MSZ * DIM;
    {   // load 64x256 tiles: 1024 16B chunks each (16KB), 8 per thread
        const char* gA = (const char*)(Z + (size_t)ti * 64 * DIM);
        const char* gB = (const char*)(Z + (size_t)tj * 64 * DIM);
        #pragma unroll
        for (int q = 0; q < 8; q++) {
            int f = t + q * 128;
            uint32_t off = swz8(f >> 4, f & 15);
            CP_ASYNC16(sA + off, gA + (size_t)f * 16);
            if (!diag) CP_ASYNC16(sBj + off, gB + (size_t)f * 16);
        }
        CP_COMMIT();
        CP_WAIT0();
        __syncthreads();
    }

    float C[2][4][4];
    #pragma unroll
    for (int mt = 0; mt < 2; mt++)
        #pragma unroll
        for (int nt = 0; nt < 4; nt++)
            #pragma unroll
            for (int e = 0; e < 4; e++) C[mt][nt][e] = 0.f;

    #pragma unroll
    for (int k = 0; k < 8; k++) {           // 8 steps of k=32 fp8
        uint32_t cb = 2u * k + (lane >> 4);
        uint32_t afr[2][4], bfr[2][4];
        #pragma unroll
        for (int mt = 0; mt < 2; mt++) {
            uint32_t r = wm * 32 + mt * 16 + (lane & 15);
            LDMATRIX_X4(afr[mt], sA + swz8(r, cb));
        }
        #pragma unroll
        for (int h = 0; h < 2; h++) {
            uint32_t r = wn * 32 + h * 16 + (lane & 15);
            LDMATRIX_X4(bfr[h], sBj + swz8(r, cb));
        }
        #pragma unroll
        for (int mt = 0; mt < 2; mt++)
            #pragma unroll
            for (int nt = 0; nt < 4; nt++) {
                uint32_t b0 = bfr[nt >> 1][(nt & 1) ? 1 : 0];
                uint32_t b1 = bfr[nt >> 1][(nt & 1) ? 3 : 2];
                MMA_FP8A(C[mt][nt], afr[mt], b0, b1);
            }
    }

    // epilogue: branch-free; one MUFU f16x2 per element-pair
    const __half2 K2H = __floats2half2_rn(0.022556390446879415f,
                                          0.022556390446879415f);
    __half2 rowh[4], colh[4];
    #pragma unroll
    for (int q = 0; q < 4; q++) { rowh[q] = __floats2half2_rn(0.f, 0.f);
                                  colh[q] = __floats2half2_rn(0.f, 0.f); }

    #pragma unroll
    for (int mt = 0; mt < 2; mt++)
        #pragma unroll
        for (int nt = 0; nt < 4; nt++)
            #pragma unroll
            for (int h = 0; h < 2; h++) {
                __half2 hv = __floats2half2_rn(C[mt][nt][h * 2 + 0],
                                               C[mt][nt][h * 2 + 1]);
                __half2 ev = ex2_h2(__hmul2(hv, K2H));
                rowh[mt * 2 + h] = __hadd2(rowh[mt * 2 + h], ev);
                colh[nt] = __hadd2(colh[nt], ev);
            }

    float rowacc[4], colacc[8];
    #pragma unroll
    for (int q = 0; q < 4; q++) {
        float2 f = __half22float2(rowh[q]);
        rowacc[q] = f.x + f.y;
    }
    #pragma unroll
    for (int nt = 0; nt < 4; nt++) {
        float2 f = __half22float2(colh[nt]);
        colacc[nt * 2 + 0] = f.x;
        colacc[nt * 2 + 1] = f.y;
    }

    // row reduction: over lane&3, then across wn via smem
    #pragma unroll
    for (int q = 0; q < 4; q++) {
        rowacc[q] += __shfl_xor_sync(0xffffffffu, rowacc[q], 1);
        rowacc[q] += __shfl_xor_sync(0xffffffffu, rowacc[q], 2);
    }
    if ((lane & 3) == 0) {
        #pragma unroll
        for (int mt = 0; mt < 2; mt++)
            #pragma unroll
            for (int h = 0; h < 2; h++)
                red[wm * 32 + mt * 16 + (lane >> 2) + 8 * h][wn] =
                    rowacc[mt * 2 + h];
    }

    // col reduction: over lane>>2 groups, then across wm via smem
    #pragma unroll
    for (int q = 0; q < 8; q++) {
        colacc[q] += __shfl_xor_sync(0xffffffffu, colacc[q], 4);
        colacc[q] += __shfl_xor_sync(0xffffffffu, colacc[q], 8);
        colacc[q] += __shfl_xor_sync(0xffffffffu, colacc[q], 16);
    }
    if (lane < 4) {
        #pragma unroll
        for (int nt = 0; nt < 4; nt++)
            #pragma unroll
            for (int e = 0; e < 2; e++)
                colred[wn * 32 + nt * 8 + lane * 2 + e][wm] =
                    colacc[nt * 2 + e];
    }
    __syncthreads();

    // slot algebra: row-side pair (ti,tj) -> tile ti slot tj;
    //               col-side pair (ti,tj) -> tile tj slot ti (skip if diag).
    if (t < 64) {
        g_rowpart[b][ti][tj][t] = red[t][0] + red[t][1];
        if (!diag)
            g_rowpart[b][tj][ti][t] = colred[t][0] + colred[t][1];
    }
}

// One block per batch; last block does the final combine.
__global__ void lse_kernel(float* __restrict__ out) {
    int b = blockIdx.x;
    int t = threadIdx.x;           // 0..511
    int tr = t >> 6, r = t & 63;
    const float* rp = &g_rowpart[b][tr][0][0];
    float s = -SELF_E2;
    #pragma unroll
    for (int q = 0; q < 8; q++) s += rp[q * 64 + r];
    float l = logf(s);

    __shared__ float wsum[16];
    #pragma unroll
    for (int o = 16; o > 0; o >>= 1)
        l += __shfl_down_sync(0xffffffffu, l, o);
    if ((t & 31) == 0) wsum[t >> 5] = l;
    __syncthreads();
    __shared__ bool last;
    if (t == 0) {
        float acc = 0.f;
        #pragma unroll
        for (int q = 0; q < 16; q++) acc += wsum[q];
        g_neg_part[b] = acc;
        __threadfence();
        unsigned o = atomicAdd(&g_ctr, 1u);
        last = (o == TWO_B - 1);
    }
    __syncthreads();
    if (!last) return;

    // final reduction (512 threads)
    __threadfence();
    double dp = 0.0, dn = 0.0;
    #pragma unroll
    for (int q = 0; q < 8; q++) dp += (double)g_pos_part[t + q * 512];
    if (t < TWO_B) dn = (double)g_neg_part[t];

    __shared__ double wp[16], wng[16];
    #pragma unroll
    for (int o = 16; o > 0; o >>= 1) {
        dp += __shfl_down_sync(0xffffffffu, dp, o);
        dn += __shfl_down_sync(0xffffffffu, dn, o);
    }
    if ((t & 31) == 0) { wp[t >> 5] = dp; wng[t >> 5] = dn; }
    __syncthreads();
    if (t == 0) {
        double sp = 0.0, sn = 0.0;
        #pragma unroll
        for (int q = 0; q < 16; q++) { sp += wp[q]; sn += wng[q]; }
        double loss_neg = sn / (double)(TWO_B * MSZ);
        double loss_pos = (sp / (double)NROWS) * 2.0;
        out[0] = (float)(loss_neg - loss_pos);
    }
}

extern "C" void kernel_launch(void* const* d_in, const int* in_sizes, int n_in,
                              void* d_out, int out_size) {
    const float* x  = (const float*)d_in[0];
    const float* xp = (const float*)d_in[1];
    float* out = (float*)d_out;

    cudaFuncSetAttribute(gram_kernel,
                         cudaFuncAttributeMaxDynamicSharedMemorySize, 32768);

    normalize_kernel<<<NROWS / 8, 256>>>(x, xp);
    dim3 grid(NP, TWO_B);   // 36 tile pairs x 128 batches
    gram_kernel<<<grid, 128, 32768>>>();
    lse_kernel<<<TWO_B, 512>>>(out);
}

// round 11
// speedup vs baseline: 1.1231x; 1.0050x over previous
#include <cuda_runtime.h>
#include <cuda_bf16.h>
#include <cuda_fp16.h>
#include <cuda_fp8.h>
#include <math.h>
#include <stdint.h>

#define TWO_B 128
#define KCH   256
#define MSZ   512
#define DIM   256
#define NROWS (TWO_B * KCH)   // 32768
#define EPSN  1e-8f
#define SELF_E2 7.38905609893065f   // exp(2) diagonal term subtracted in lse
#define NP 36                       // 8*9/2 tile pairs (64-row tiles)

// fp8 normalized rows, batch-major [b][i][d], scaled by 16/sqrt(2): 16 MB
__device__ uint8_t g_z8[(size_t)TWO_B * MSZ * DIM];
// per-row exp-sum partials: [b][row_tile(8)][slot(8)][row(64)], each written once
__device__ float g_rowpart[TWO_B][8][8][64];   // 1 MB
__device__ float g_pos_part[NROWS / 16];       // per normalize block (16 rows)
__device__ float g_neg_part[TWO_B];
__device__ unsigned g_ctr;

__constant__ unsigned char TI_LUT[NP] = {
    0,0,0,0,0,0,0,0, 1,1,1,1,1,1,1, 2,2,2,2,2,2, 3,3,3,3,3,
    4,4,4,4, 5,5,5, 6,6, 7};
__constant__ unsigned char TJ_LUT[NP] = {
    0,1,2,3,4,5,6,7, 1,2,3,4,5,6,7, 2,3,4,5,6,7, 3,4,5,6,7,
    4,5,6,7, 5,6,7, 6,7, 7};

// ---------------- helpers ----------------
__device__ __forceinline__ uint32_t smem_u32(const void* p) {
    uint32_t a;
    asm("{ .reg .u64 t; cvta.to.shared.u64 t, %1; cvt.u32.u64 %0, t; }"
        : "=r"(a) : "l"(p));
    return a;
}

#define CP_ASYNC16(sdst, gsrc) \
    asm volatile("cp.async.cg.shared.global [%0], [%1], 16;" \
                 :: "r"(sdst), "l"(gsrc) : "memory")
#define CP_COMMIT() asm volatile("cp.async.commit_group;" ::: "memory")
#define CP_WAIT0()  asm volatile("cp.async.wait_group 0;" ::: "memory")

#define LDMATRIX_X4(r, addr) \
    asm volatile("ldmatrix.sync.aligned.m8n8.x4.shared.b16 {%0,%1,%2,%3}, [%4];" \
                 : "=r"((r)[0]), "=r"((r)[1]), "=r"((r)[2]), "=r"((r)[3]) \
                 : "r"(addr))

#define MMA_FP8A(c, a, b0, b1) \
    asm volatile("mma.sync.aligned.m16n8k32.row.col.f32.e4m3.e4m3.f32 " \
                 "{%0,%1,%2,%3},{%4,%5,%6,%7},{%8,%9},{%0,%1,%2,%3};" \
                 : "+f"((c)[0]), "+f"((c)[1]), "+f"((c)[2]), "+f"((c)[3]) \
                 : "r"((a)[0]), "r"((a)[1]), "r"((a)[2]), "r"((a)[3]), \
                   "r"(b0), "r"(b1))

// 64 rows x 256 fp8 tile (256B/row); cb = 16B column 0..15, XOR-swizzled
__device__ __forceinline__ uint32_t swz8(uint32_t r, uint32_t cb) {
    return r * 256u + ((cb ^ (r & 7u)) << 4);
}

__device__ __forceinline__ uint32_t pack_fp8x4(float a, float b, float c, float d) {
    __nv_fp8x2_storage_t lo = __nv_cvt_float2_to_fp8x2(make_float2(a, b),
                                                       __NV_SATFINITE, __NV_E4M3);
    __nv_fp8x2_storage_t hi = __nv_cvt_float2_to_fp8x2(make_float2(c, d),
                                                       __NV_SATFINITE, __NV_E4M3);
    return (uint32_t)lo | ((uint32_t)hi << 16);
}

// half2 2^x via MUFU (both lanes in one op)
__device__ __forceinline__ __half2 ex2_h2(__half2 v) {
    uint32_t r, a = *(uint32_t*)&v;
    asm("ex2.approx.f16x2 %0, %1;" : "=r"(r) : "r"(a));
    return *(__half2*)&r;
}

// streaming float4 load (evict-first: don't pollute L2 against g_z8)
__device__ __forceinline__ float4 ldcs4(const float4* p) {
    float4 v;
    asm volatile("ld.global.cs.v4.f32 {%0,%1,%2,%3}, [%4];"
                 : "=f"(v.x), "=f"(v.y), "=f"(v.z), "=f"(v.w) : "l"(p));
    return v;
}

// ---------------- kernels ----------------
// One warp per TWO rows (8 LDG.128 in flight): norms + cosine; write scaled
// normalized fp8 rows batch-major.
__global__ void normalize_kernel(const float* __restrict__ x,
                                 const float* __restrict__ xp) {
    if (blockIdx.x == 0 && threadIdx.x == 0) g_ctr = 0;

    int wib  = threadIdx.x >> 5;
    int lane = threadIdx.x & 31;
    int row0 = blockIdx.x * 16 + wib * 2;    // this warp: row0, row0+1

    const float4* xr0 = (const float4*)(x  + (size_t)row0 * DIM);
    const float4* pr0 = (const float4*)(xp + (size_t)row0 * DIM);
    const float4* xr1 = (const float4*)(x  + (size_t)(row0 + 1) * DIM);
    const float4* pr1 = (const float4*)(xp + (size_t)(row0 + 1) * DIM);

    // 8 independent 16B loads up front (MLP 8)
    float4 xa0 = ldcs4(xr0 + lane),      xb0 = ldcs4(xr0 + lane + 32);
    float4 pa0 = ldcs4(pr0 + lane),      pb0 = ldcs4(pr0 + lane + 32);
    float4 xa1 = ldcs4(xr1 + lane),      xb1 = ldcs4(xr1 + lane + 32);
    float4 pa1 = ldcs4(pr1 + lane),      pb1 = ldcs4(pr1 + lane + 32);

    float ssx0 = xa0.x*xa0.x + xa0.y*xa0.y + xa0.z*xa0.z + xa0.w*xa0.w
               + xb0.x*xb0.x + xb0.y*xb0.y + xb0.z*xb0.z + xb0.w*xb0.w;
    float ssp0 = pa0.x*pa0.x + pa0.y*pa0.y + pa0.z*pa0.z + pa0.w*pa0.w
               + pb0.x*pb0.x + pb0.y*pb0.y + pb0.z*pb0.z + pb0.w*pb0.w;
    float dt0  = xa0.x*pa0.x + xa0.y*pa0.y + xa0.z*pa0.z + xa0.w*pa0.w
               + xb0.x*pb0.x + xb0.y*pb0.y + xb0.z*pb0.z + xb0.w*pb0.w;
    float ssx1 = xa1.x*xa1.x + xa1.y*xa1.y + xa1.z*xa1.z + xa1.w*xa1.w
               + xb1.x*xb1.x + xb1.y*xb1.y + xb1.z*xb1.z + xb1.w*xb1.w;
    float ssp1 = pa1.x*pa1.x + pa1.y*pa1.y + pa1.z*pa1.z + pa1.w*pa1.w
               + pb1.x*pb1.x + pb1.y*pb1.y + pb1.z*pb1.z + pb1.w*pb1.w;
    float dt1  = xa1.x*pa1.x + xa1.y*pa1.y + xa1.z*pa1.z + xa1.w*pa1.w
               + xb1.x*pb1.x + xb1.y*pb1.y + xb1.z*pb1.z + xb1.w*pb1.w;

    #pragma unroll
    for (int o = 16; o > 0; o >>= 1) {
        ssx0 += __shfl_xor_sync(0xffffffffu, ssx0, o);
        ssp0 += __shfl_xor_sync(0xffffffffu, ssp0, o);
        dt0  += __shfl_xor_sync(0xffffffffu, dt0,  o);
        ssx1 += __shfl_xor_sync(0xffffffffu, ssx1, o);
        ssp1 += __shfl_xor_sync(0xffffffffu, ssp1, o);
        dt1  += __shfl_xor_sync(0xffffffffu, dt1,  o);
    }

    float nx0 = fmaxf(sqrtf(ssx0), EPSN), np0 = fmaxf(sqrtf(ssp0), EPSN);
    float nx1 = fmaxf(sqrtf(ssx1), EPSN), np1 = fmaxf(sqrtf(ssp1), EPSN);
    float cos0 = dt0 / (nx0 * np0);
    float cos1 = dt1 / (nx1 * np1);

    // scale = 16/sqrt(2): stored dot = 128*cos = c, sim/TEMP = c/64
    const float SCL = 11.313708498984761f;
    float sx0 = SCL / nx0, sp0 = SCL / np0;
    float sx1 = SCL / nx1, sp1 = SCL / np1;

    int b0 = row0 & (TWO_B - 1), i0 = row0 >> 7;
    int b1 = (row0 + 1) & (TWO_B - 1), i1 = (row0 + 1) >> 7;

    uint8_t* zx0 = g_z8 + ((size_t)b0 * MSZ + i0)       * DIM;
    uint8_t* zp0 = g_z8 + ((size_t)b0 * MSZ + i0 + KCH) * DIM;
    uint8_t* zx1 = g_z8 + ((size_t)b1 * MSZ + i1)       * DIM;
    uint8_t* zp1 = g_z8 + ((size_t)b1 * MSZ + i1 + KCH) * DIM;
    *(uint32_t*)(zx0 + 4*lane)       = pack_fp8x4(xa0.x*sx0, xa0.y*sx0, xa0.z*sx0, xa0.w*sx0);
    *(uint32_t*)(zx0 + 128 + 4*lane) = pack_fp8x4(xb0.x*sx0, xb0.y*sx0, xb0.z*sx0, xb0.w*sx0);
    *(uint32_t*)(zp0 + 4*lane)       = pack_fp8x4(pa0.x*sp0, pa0.y*sp0, pa0.z*sp0, pa0.w*sp0);
    *(uint32_t*)(zp0 + 128 + 4*lane) = pack_fp8x4(pb0.x*sp0, pb0.y*sp0, pb0.z*sp0, pb0.w*sp0);
    *(uint32_t*)(zx1 + 4*lane)       = pack_fp8x4(xa1.x*sx1, xa1.y*sx1, xa1.z*sx1, xa1.w*sx1);
    *(uint32_t*)(zx1 + 128 + 4*lane) = pack_fp8x4(xb1.x*sx1, xb1.y*sx1, xb1.z*sx1, xb1.w*sx1);
    *(uint32_t*)(zp1 + 4*lane)       = pack_fp8x4(pa1.x*sp1, pa1.y*sp1, pa1.z*sp1, pa1.w*sp1);
    *(uint32_t*)(zp1 + 128 + 4*lane) = pack_fp8x4(pb1.x*sp1, pb1.y*sp1, pb1.z*sp1, pb1.w*sp1);

    __shared__ float psum[8];
    if (lane == 0) psum[wib] = cos0 + cos1;
    __syncthreads();
    if (threadIdx.x == 0) {
        float s = 0.f;
        #pragma unroll
        for (int q = 0; q < 8; q++) s += psum[q];
        g_pos_part[blockIdx.x] = s;
    }
}

// One CTA = one (b, ti<=tj) 64x64 tile pair. 4 warps, high occupancy.
__global__ __launch_bounds__(128, 6) void gram_kernel() {
    __shared__ float red[64][2];
    __shared__ float colred[64][2];
    extern __shared__ char dyn[];

    int t    = threadIdx.x;
    int wid  = t >> 5;
    int lane = t & 31;
    int b    = blockIdx.y;
    int p    = blockIdx.x;
    int ti   = TI_LUT[p];
    int tj   = TJ_LUT[p];
    bool diag = (ti == tj);

    int wm = wid >> 1;          // 0..1 : warp m-offset = wm*32
    int wn = wid & 1;           // 0..1 : warp n-offset = wn*32

    uint32_t sA = smem_u32(dyn);
    uint32_t sBj = diag ? sA : (sA + 16384);

    const uint8_t* Z = g_z8 + (size_t)b * MSZ * DIM;
    {   // load 64x256 tiles: 1024 16B chunks each (16KB), 8 per thread
        const char* gA = (const char*)(Z + (size_t)ti * 64 * DIM);
        const char* gB = (const char*)(Z + (size_t)tj * 64 * DIM);
        #pragma unroll
        for (int q = 0; q < 8; q++) {
            int f = t + q * 128;
            uint32_t off = swz8(f >> 4, f & 15);
            CP_ASYNC16(sA + off, gA + (size_t)f * 16);
            if (!diag) CP_ASYNC16(sBj + off, gB + (size_t)f * 16);
        }
        CP_COMMIT();
        CP_WAIT0();
        __syncthreads();
    }

    float C[2][4][4];
    #pragma unroll
    for (int mt = 0; mt < 2; mt++)
        #pragma unroll
        for (int nt = 0; nt < 4; nt++)
            #pragma unroll
            for (int e = 0; e < 4; e++) C[mt][nt][e] = 0.f;

    #pragma unroll
    for (int k = 0; k < 8; k++) {           // 8 steps of k=32 fp8
        uint32_t cb = 2u * k + (lane >> 4);
        uint32_t afr[2][4], bfr[2][4];
        #pragma unroll
        for (int mt = 0; mt < 2; mt++) {
            uint32_t r = wm * 32 + mt * 16 + (lane & 15);
            LDMATRIX_X4(afr[mt], sA + swz8(r, cb));
        }
        #pragma unroll
        for (int h = 0; h < 2; h++) {
            uint32_t r = wn * 32 + h * 16 + (lane & 15);
            LDMATRIX_X4(bfr[h], sBj + swz8(r, cb));
        }
        #pragma unroll
        for (int mt = 0; mt < 2; mt++)
            #pragma unroll
            for (int nt = 0; nt < 4; nt++) {
                uint32_t b0 = bfr[nt >> 1][(nt & 1) ? 1 : 0];
                uint32_t b1 = bfr[nt >> 1][(nt & 1) ? 3 : 2];
                MMA_FP8A(C[mt][nt], afr[mt], b0, b1);
            }
    }

    // epilogue: branch-free; one MUFU f16x2 per element-pair
    const __half2 K2H = __floats2half2_rn(0.022556390446879415f,
                                          0.022556390446879415f);
    __half2 rowh[4], colh[4];
    #pragma unroll
    for (int q = 0; q < 4; q++) { rowh[q] = __floats2half2_rn(0.f, 0.f);
                                  colh[q] = __floats2half2_rn(0.f, 0.f); }

    #pragma unroll
    for (int mt = 0; mt < 2; mt++)
        #pragma unroll
        for (int nt = 0; nt < 4; nt++)
            #pragma unroll
            for (int h = 0; h < 2; h++) {
                __half2 hv = __floats2half2_rn(C[mt][nt][h * 2 + 0],
                                               C[mt][nt][h * 2 + 1]);
                __half2 ev = ex2_h2(__hmul2(hv, K2H));
                rowh[mt * 2 + h] = __hadd2(rowh[mt * 2 + h], ev);
                colh[nt] = __hadd2(colh[nt], ev);
            }

    float rowacc[4], colacc[8];
    #pragma unroll
    for (int q = 0; q < 4; q++) {
        float2 f = __half22float2(rowh[q]);
        rowacc[q] = f.x + f.y;
    }
    #pragma unroll
    for (int nt = 0; nt < 4; nt++) {
        float2 f = __half22float2(colh[nt]);
        colacc[nt * 2 + 0] = f.x;
        colacc[nt * 2 + 1] = f.y;
    }

    // row reduction: over lane&3, then across wn via smem
    #pragma unroll
    for (int q = 0; q < 4; q++) {
        rowacc[q] += __shfl_xor_sync(0xffffffffu, rowacc[q], 1);
        rowacc[q] += __shfl_xor_sync(0xffffffffu, rowacc[q], 2);
    }
    if ((lane & 3) == 0) {
        #pragma unroll
        for (int mt = 0; mt < 2; mt++)
            #pragma unroll
            for (int h = 0; h < 2; h++)
                red[wm * 32 + mt * 16 + (lane >> 2) + 8 * h][wn] =
                    rowacc[mt * 2 + h];
    }

    // col reduction: over lane>>2 groups, then across wm via smem
    #pragma unroll
    for (int q = 0; q < 8; q++) {
        colacc[q] += __shfl_xor_sync(0xffffffffu, colacc[q], 4);
        colacc[q] += __shfl_xor_sync(0xffffffffu, colacc[q], 8);
        colacc[q] += __shfl_xor_sync(0xffffffffu, colacc[q], 16);
    }
    if (lane < 4) {
        #pragma unroll
        for (int nt = 0; nt < 4; nt++)
            #pragma unroll
            for (int e = 0; e < 2; e++)
                colred[wn * 32 + nt * 8 + lane * 2 + e][wm] =
                    colacc[nt * 2 + e];
    }
    __syncthreads();

    // slot algebra: row-side pair (ti,tj) -> tile ti slot tj;
    //               col-side pair (ti,tj) -> tile tj slot ti (skip if diag).
    if (t < 64) {
        g_rowpart[b][ti][tj][t] = red[t][0] + red[t][1];
        if (!diag)
            g_rowpart[b][tj][ti][t] = colred[t][0] + colred[t][1];
    }
}

// One block per batch; last block does the final combine.
__global__ void lse_kernel(float* __restrict__ out) {
    int b = blockIdx.x;
    int t = threadIdx.x;           // 0..511
    int tr = t >> 6, r = t & 63;
    const float* rp = &g_rowpart[b][tr][0][0];
    float s = -SELF_E2;
    #pragma unroll
    for (int q = 0; q < 8; q++) s += rp[q * 64 + r];
    float l = logf(s);

    __shared__ float wsum[16];
    #pragma unroll
    for (int o = 16; o > 0; o >>= 1)
        l += __shfl_down_sync(0xffffffffu, l, o);
    if ((t & 31) == 0) wsum[t >> 5] = l;
    __syncthreads();
    __shared__ bool last;
    if (t == 0) {
        float acc = 0.f;
        #pragma unroll
        for (int q = 0; q < 16; q++) acc += wsum[q];
        g_neg_part[b] = acc;
        __threadfence();
        unsigned o = atomicAdd(&g_ctr, 1u);
        last = (o == TWO_B - 1);
    }
    __syncthreads();
    if (!last) return;

    // final reduction (512 threads)
    __threadfence();
    double dp = 0.0, dn = 0.0;
    #pragma unroll
    for (int q = 0; q < 4; q++) dp += (double)g_pos_part[t + q * 512];
    if (t < TWO_B) dn = (double)g_neg_part[t];

    __shared__ double wp[16], wng[16];
    #pragma unroll
    for (int o = 16; o > 0; o >>= 1) {
        dp += __shfl_down_sync(0xffffffffu, dp, o);
        dn += __shfl_down_sync(0xffffffffu, dn, o);
    }
    if ((t & 31) == 0) { wp[t >> 5] = dp; wng[t >> 5] = dn; }
    __syncthreads();
    if (t == 0) {
        double sp = 0.0, sn = 0.0;
        #pragma unroll
        for (int q = 0; q < 16; q++) { sp += wp[q]; sn += wng[q]; }
        double loss_neg = sn / (double)(TWO_B * MSZ);
        double loss_pos = (sp / (double)NROWS) * 2.0;
        out[0] = (float)(loss_neg - loss_pos);
    }
}

extern "C" void kernel_launch(void* const* d_in, const int* in_sizes, int n_in,
                              void* d_out, int out_size) {
    const float* x  = (const float*)d_in[0];
    const float* xp = (const float*)d_in[1];
    float* out = (float*)d_out;

    cudaFuncSetAttribute(gram_kernel,
                         cudaFuncAttributeMaxDynamicSharedMemorySize, 32768);

    normalize_kernel<<<NROWS / 16, 256>>>(x, xp);
    dim3 grid(NP, TWO_B);   // 36 tile pairs x 128 batches
    gram_kernel<<<grid, 128, 32768>>>();
    lse_kernel<<<TWO_B, 512>>>(out);
}